// round 1
// baseline (speedup 1.0000x reference)
#include <cuda_runtime.h>
#include <cstdint>

// Problem constants
#define BB 4
#define SS 2048
#define DD 1024
#define HH 16
#define DKK 64
#define MM (BB*SS)          // 8192
#define OUT_PLANE (BB*SS*DD) // 8388608

// Scratch (allocation-free rule: __device__ globals)
__device__ float g_Qh[BB*HH*SS*DKK];   // Q projected, head layout
__device__ float g_ctx[BB*SS*DD];      // attention context, [B,S,D]

// ---------------------------------------------------------------------------
// GEMM: C[m,e] = sum_d A[m,d] * W[e,d]   (A: [8192,1024], W: [1024,1024])
// 128x128 tile, BK=8, 256 threads, 8x8 micro-tile.
// head_layout: write out[((b*16+h)*2048+s)*64+dk], else out[m*1024+e]
// ---------------------------------------------------------------------------
__global__ __launch_bounds__(256) void gemm_k(const float* __restrict__ A,
                                              const float* __restrict__ W,
                                              float* __restrict__ out,
                                              int head_layout)
{
    __shared__ float As[8][128];
    __shared__ float Bs[8][128];

    const int tid = threadIdx.x;
    const int tx = tid & 15;
    const int ty = tid >> 4;
    const int m0 = blockIdx.y << 7;
    const int n0 = blockIdx.x << 7;

    const int lr = tid >> 1;          // 0..127
    const int lc = (tid & 1) << 2;    // 0 or 4

    const float* Ap = A + (size_t)(m0 + lr) * DD + lc;
    const float* Bp = W + (size_t)(n0 + lr) * DD + lc;

    float acc[8][8];
#pragma unroll
    for (int i = 0; i < 8; i++)
#pragma unroll
        for (int j = 0; j < 8; j++) acc[i][j] = 0.0f;

    for (int k0 = 0; k0 < DD; k0 += 8) {
        float4 av = *(const float4*)(Ap + k0);
        float4 bv = *(const float4*)(Bp + k0);
        __syncthreads();
        As[lc + 0][lr] = av.x; As[lc + 1][lr] = av.y;
        As[lc + 2][lr] = av.z; As[lc + 3][lr] = av.w;
        Bs[lc + 0][lr] = bv.x; Bs[lc + 1][lr] = bv.y;
        Bs[lc + 2][lr] = bv.z; Bs[lc + 3][lr] = bv.w;
        __syncthreads();
#pragma unroll
        for (int kk = 0; kk < 8; kk++) {
            float4 a0 = *(const float4*)&As[kk][ty << 3];
            float4 a1 = *(const float4*)&As[kk][(ty << 3) + 4];
            float4 b0 = *(const float4*)&Bs[kk][tx << 3];
            float4 b1 = *(const float4*)&Bs[kk][(tx << 3) + 4];
            float ra[8] = {a0.x, a0.y, a0.z, a0.w, a1.x, a1.y, a1.z, a1.w};
            float rb[8] = {b0.x, b0.y, b0.z, b0.w, b1.x, b1.y, b1.z, b1.w};
#pragma unroll
            for (int i = 0; i < 8; i++)
#pragma unroll
                for (int j = 0; j < 8; j++)
                    acc[i][j] += ra[i] * rb[j];
        }
    }

#pragma unroll
    for (int i = 0; i < 8; i++) {
        int m = m0 + (ty << 3) + i;
        int b = m >> 11;
        int s = m & 2047;
#pragma unroll
        for (int j = 0; j < 8; j++) {
            int e = n0 + (tx << 3) + j;
            if (head_layout) {
                int h = e >> 6, dk = e & 63;
                out[((((size_t)b * HH + h) << 11) + s) * DKK + dk] = acc[i][j];
            } else {
                out[(size_t)m * DD + e] = acc[i][j];
            }
        }
    }
}

// ---------------------------------------------------------------------------
// Causal flash attention. Grid: (S/64, B*H). Block: 256 threads.
// Q,K,V in [B,H,S,DK]. Writes ctx in [B,S,D] (head concat).
// Smem: exactly 48KB: Qs(16K) + KPs(16K, K tile then P tile) + Vs(16K).
// ---------------------------------------------------------------------------
__global__ __launch_bounds__(256) void attn_k(const float* __restrict__ Q,
                                              const float* __restrict__ K,
                                              const float* __restrict__ V,
                                              float* __restrict__ ctx)
{
    __shared__ float Qs[64][64];   // [d][row], pre-scaled
    __shared__ float KPs[64][64];  // K: [d][key^swz]; later P: [key][row^swz]
    __shared__ float Vs[64][64];   // [key][d]

    const int tid = threadIdx.x;
    const int tx = tid & 15;
    const int ty = tid >> 4;
    const int qt = blockIdx.x;
    const int bh = blockIdx.y;

    const size_t base = (size_t)bh * SS * DKK;
    const float* Qb = Q + base + (size_t)qt * 64 * DKK;
    const float* Kb = K + base;
    const float* Vb = V + base;
    const float scale = 0.125f;   // 1/sqrt(64)

    // Load Q tile transposed, pre-scaled
#pragma unroll
    for (int u = 0; u < 4; u++) {
        int fi = u * 256 + tid;
        int r = fi >> 4;
        int c = (fi & 15) << 2;
        float4 v = *(const float4*)(Qb + r * DKK + c);
        Qs[c + 0][r] = v.x * scale;
        Qs[c + 1][r] = v.y * scale;
        Qs[c + 2][r] = v.z * scale;
        Qs[c + 3][r] = v.w * scale;
    }

    float accO[4][4];
#pragma unroll
    for (int i = 0; i < 4; i++)
#pragma unroll
        for (int j = 0; j < 4; j++) accO[i][j] = 0.0f;
    float mr[4] = {-1e30f, -1e30f, -1e30f, -1e30f};
    float lr_[4] = {0.0f, 0.0f, 0.0f, 0.0f};

    for (int kt = 0; kt <= qt; kt++) {
        __syncthreads();   // previous iteration done with KPs/Vs
        const float* Kt = Kb + (size_t)kt * 64 * DKK;
        const float* Vt = Vb + (size_t)kt * 64 * DKK;
#pragma unroll
        for (int u = 0; u < 4; u++) {
            int fi = u * 256 + tid;
            int r = fi >> 4;          // key
            int c = (fi & 15) << 2;   // d
            float4 kv = *(const float4*)(Kt + r * DKK + c);
            int rs = r ^ ((c >> 2) & 15);
            KPs[c + 0][rs] = kv.x;
            KPs[c + 1][rs] = kv.y;
            KPs[c + 2][rs] = kv.z;
            KPs[c + 3][rs] = kv.w;
            float4 vv = *(const float4*)(Vt + r * DKK + c);
            *(float4*)&Vs[r][c] = vv;
        }
        __syncthreads();

        // GEMM1: S = Q @ K^T
        float sacc[4][4];
#pragma unroll
        for (int i = 0; i < 4; i++)
#pragma unroll
            for (int j = 0; j < 4; j++) sacc[i][j] = 0.0f;

#pragma unroll 8
        for (int kk = 0; kk < 64; kk++) {
            float4 qa = *(const float4*)&Qs[kk][ty << 2];
            float ra[4] = {qa.x, qa.y, qa.z, qa.w};
            int sw = (kk >> 2) & 15;
            float rb[4];
#pragma unroll
            for (int j = 0; j < 4; j++)
                rb[j] = KPs[kk][((tx << 2) + j) ^ sw];
#pragma unroll
            for (int i = 0; i < 4; i++)
#pragma unroll
                for (int j = 0; j < 4; j++)
                    sacc[i][j] += ra[i] * rb[j];
        }

        if (kt == qt) {
#pragma unroll
            for (int i = 0; i < 4; i++)
#pragma unroll
                for (int j = 0; j < 4; j++)
                    if ((tx << 2) + j > (ty << 2) + i) sacc[i][j] = -1e30f;
        }

        // Online softmax: rows split across 16 lanes (width-16 shfl reduce)
#pragma unroll
        for (int i = 0; i < 4; i++) {
            float rm = fmaxf(fmaxf(sacc[i][0], sacc[i][1]),
                             fmaxf(sacc[i][2], sacc[i][3]));
#pragma unroll
            for (int o = 1; o < 16; o <<= 1)
                rm = fmaxf(rm, __shfl_xor_sync(0xFFFFFFFFu, rm, o, 16));
            float mnew = fmaxf(mr[i], rm);
            float al = __expf(mr[i] - mnew);
            float rs = 0.0f;
#pragma unroll
            for (int j = 0; j < 4; j++) {
                float p = __expf(sacc[i][j] - mnew);
                sacc[i][j] = p;
                rs += p;
            }
#pragma unroll
            for (int o = 1; o < 16; o <<= 1)
                rs += __shfl_xor_sync(0xFFFFFFFFu, rs, o, 16);
            lr_[i] = lr_[i] * al + rs;
            mr[i] = mnew;
#pragma unroll
            for (int j = 0; j < 4; j++) accO[i][j] *= al;
        }

        __syncthreads();   // all GEMM1 reads of KPs done
        // Write P into KPs: [key][row ^ ((key>>2)&15)]; key=4tx+j -> swz = tx
#pragma unroll
        for (int j = 0; j < 4; j++)
#pragma unroll
            for (int i = 0; i < 4; i++)
                KPs[(tx << 2) + j][((ty << 2) + i) ^ tx] = sacc[i][j];
        __syncthreads();

        // GEMM2: O += P @ V
#pragma unroll 8
        for (int kk = 0; kk < 64; kk++) {
            int sw = (kk >> 2) & 15;
            float ra[4];
#pragma unroll
            for (int i = 0; i < 4; i++)
                ra[i] = KPs[kk][((ty << 2) + i) ^ sw];
            float4 vb = *(const float4*)&Vs[kk][tx << 2];
            float rb[4] = {vb.x, vb.y, vb.z, vb.w};
#pragma unroll
            for (int i = 0; i < 4; i++)
#pragma unroll
                for (int j = 0; j < 4; j++)
                    accO[i][j] += ra[i] * rb[j];
        }
    }

    // Epilogue: normalize, write ctx [B,S,D] with head concat
    const int b = bh >> 4;
    const int h = bh & 15;
#pragma unroll
    for (int i = 0; i < 4; i++) {
        float inv = 1.0f / lr_[i];
        int sg = (qt << 6) + (ty << 2) + i;
#pragma unroll
        for (int j = 0; j < 4; j++) {
            int e = (h << 6) + (tx << 2) + j;
            ctx[((size_t)b * SS + sg) * DD + e] = accO[i][j] * inv;
        }
    }
}

// ---------------------------------------------------------------------------
extern "C" void kernel_launch(void* const* d_in, const int* in_sizes, int n_in,
                              void* d_out, int out_size)
{
    const float* q   = (const float*)d_in[0];
    const float* k   = (const float*)d_in[1];
    const float* v   = (const float*)d_in[2];
    // d_in[3] = mask (causal tril) — computed analytically in-kernel
    const float* w_q = (const float*)d_in[4];
    const float* w_k = (const float*)d_in[5];
    const float* w_v = (const float*)d_in[6];
    const float* w_o = (const float*)d_in[7];

    float* out  = (float*)d_out;
    float* keyh = out + OUT_PLANE;
    float* valh = out + 2 * (size_t)OUT_PLANE;

    float* qh = nullptr;
    float* ctx = nullptr;
    cudaGetSymbolAddress((void**)&qh, g_Qh);
    cudaGetSymbolAddress((void**)&ctx, g_ctx);

    dim3 ggrid(DD / 128, MM / 128);   // (8, 64)
    gemm_k<<<ggrid, 256>>>(q, w_q, qh, 1);
    gemm_k<<<ggrid, 256>>>(k, w_k, keyh, 1);
    gemm_k<<<ggrid, 256>>>(v, w_v, valh, 1);

    dim3 agrid(SS / 64, BB * HH);     // (32, 64)
    attn_k<<<agrid, 256>>>(qh, keyh, valh, ctx);

    gemm_k<<<ggrid, 256>>>(ctx, w_o, out, 0);
}

// round 2
// speedup vs baseline: 2.9213x; 2.9213x over previous
#include <cuda_runtime.h>
#include <cstdint>

// Problem constants
#define BB 4
#define SS 2048
#define DD 1024
#define HH 16
#define DKK 64
#define MM (BB*SS)            // 8192
#define OUT_PLANE (BB*SS*DD)  // 8388608

// Scratch (allocation-free rule: __device__ globals)
__device__ float g_Qh[BB*HH*SS*DKK];   // Q projected, head layout
__device__ float g_ctx[BB*SS*DD];      // attention context, [B,S,D]

// ---------------------------------------------------------------------------
// helpers
// ---------------------------------------------------------------------------
__device__ __forceinline__ float to_tf32(float x) {
    uint32_t u;
    asm("cvt.rna.tf32.f32 %0, %1;" : "=r"(u) : "f"(x));
    return __uint_as_float(u);
}

// D += A(16x8) * B(8x8), tf32 inputs, fp32 accum
__device__ __forceinline__ void mma8(float* c, float a0, float a1, float a2, float a3,
                                     float b0, float b1) {
    asm volatile(
        "mma.sync.aligned.m16n8k8.row.col.f32.tf32.tf32.f32 "
        "{%0,%1,%2,%3}, {%4,%5,%6,%7}, {%8,%9}, {%0,%1,%2,%3};\n"
        : "+f"(c[0]), "+f"(c[1]), "+f"(c[2]), "+f"(c[3])
        : "r"(__float_as_uint(a0)), "r"(__float_as_uint(a1)),
          "r"(__float_as_uint(a2)), "r"(__float_as_uint(a3)),
          "r"(__float_as_uint(b0)), "r"(__float_as_uint(b1)));
}

// ---------------------------------------------------------------------------
// TF32 GEMM: C[m,e] = sum_d A[m,d] * W[e,d]
// A: [8192,1024] row-major, W: [1024,1024] row-major ([e][d] == B col-major fit)
// Block tile 128x128, BK=16, 256 threads = 8 warps (4 M x 2 N), warp = 32x64.
// head_layout: out[((b*16+h)*2048+s)*64+dk], else out[m*1024+e]
// ---------------------------------------------------------------------------
#define GP 20   // smem row pad (floats); (20g+tig)%32 distinct across warp
__global__ __launch_bounds__(256) void gemm_tc(const float* __restrict__ A,
                                               const float* __restrict__ W,
                                               float* __restrict__ out,
                                               int head_layout)
{
    __shared__ __align__(16) float As[128][GP];   // [m][k]
    __shared__ __align__(16) float Bs[128][GP];   // [n][k]

    const int tid  = threadIdx.x;
    const int lane = tid & 31;
    const int w    = tid >> 5;
    const int wm   = w & 3;          // 0..3  (M)
    const int wn   = w >> 2;         // 0..1  (N)
    const int g    = lane >> 2;      // 0..7
    const int tig  = lane & 3;       // 0..3

    const int m0 = blockIdx.y << 7;
    const int n0 = blockIdx.x << 7;

    const float* Ap = A + (size_t)m0 * DD;
    const float* Wp = W + (size_t)n0 * DD;

    // each thread loads 2 float4 per tile per matrix: idx = tid, tid+256
    const int lr  = tid >> 2;        // 0..63
    const int lc4 = tid & 3;         // 0..3

    float acc[2][8][4];
#pragma unroll
    for (int mf = 0; mf < 2; mf++)
#pragma unroll
        for (int nf = 0; nf < 8; nf++)
#pragma unroll
            for (int r = 0; r < 4; r++) acc[mf][nf][r] = 0.0f;

    for (int k0 = 0; k0 < DD; k0 += 16) {
        float4 av0 = *(const float4*)(Ap + (size_t)lr        * DD + k0 + lc4 * 4);
        float4 av1 = *(const float4*)(Ap + (size_t)(lr + 64) * DD + k0 + lc4 * 4);
        float4 bv0 = *(const float4*)(Wp + (size_t)lr        * DD + k0 + lc4 * 4);
        float4 bv1 = *(const float4*)(Wp + (size_t)(lr + 64) * DD + k0 + lc4 * 4);
        __syncthreads();
        {
            uint4 s;
            s.x = __float_as_uint(to_tf32(av0.x)); s.y = __float_as_uint(to_tf32(av0.y));
            s.z = __float_as_uint(to_tf32(av0.z)); s.w = __float_as_uint(to_tf32(av0.w));
            *(uint4*)&As[lr][lc4 * 4] = s;
            s.x = __float_as_uint(to_tf32(av1.x)); s.y = __float_as_uint(to_tf32(av1.y));
            s.z = __float_as_uint(to_tf32(av1.z)); s.w = __float_as_uint(to_tf32(av1.w));
            *(uint4*)&As[lr + 64][lc4 * 4] = s;
            s.x = __float_as_uint(to_tf32(bv0.x)); s.y = __float_as_uint(to_tf32(bv0.y));
            s.z = __float_as_uint(to_tf32(bv0.z)); s.w = __float_as_uint(to_tf32(bv0.w));
            *(uint4*)&Bs[lr][lc4 * 4] = s;
            s.x = __float_as_uint(to_tf32(bv1.x)); s.y = __float_as_uint(to_tf32(bv1.y));
            s.z = __float_as_uint(to_tf32(bv1.z)); s.w = __float_as_uint(to_tf32(bv1.w));
            *(uint4*)&Bs[lr + 64][lc4 * 4] = s;
        }
        __syncthreads();

#pragma unroll
        for (int ks = 0; ks < 2; ks++) {
            float a[2][4];
#pragma unroll
            for (int mf = 0; mf < 2; mf++) {
                int rr = (wm << 5) + (mf << 4);
                a[mf][0] = As[rr + g    ][ks * 8 + tig];
                a[mf][1] = As[rr + g + 8][ks * 8 + tig];
                a[mf][2] = As[rr + g    ][ks * 8 + tig + 4];
                a[mf][3] = As[rr + g + 8][ks * 8 + tig + 4];
            }
#pragma unroll
            for (int nf = 0; nf < 8; nf++) {
                int nr = (wn << 6) + (nf << 3) + g;
                float b0 = Bs[nr][ks * 8 + tig];
                float b1 = Bs[nr][ks * 8 + tig + 4];
                mma8(acc[0][nf], a[0][0], a[0][1], a[0][2], a[0][3], b0, b1);
                mma8(acc[1][nf], a[1][0], a[1][1], a[1][2], a[1][3], b0, b1);
            }
        }
    }

    // epilogue
#pragma unroll
    for (int mf = 0; mf < 2; mf++) {
#pragma unroll
        for (int half = 0; half < 2; half++) {
            int m = m0 + (wm << 5) + (mf << 4) + g + half * 8;
            int b = m >> 11;
            int s = m & 2047;
#pragma unroll
            for (int nf = 0; nf < 8; nf++) {
                int e = n0 + (wn << 6) + (nf << 3) + (tig << 1);
                float2 val;
                val.x = acc[mf][nf][half * 2 + 0];
                val.y = acc[mf][nf][half * 2 + 1];
                if (head_layout) {
                    int h = e >> 6, dk = e & 63;
                    *(float2*)&out[((((size_t)b * HH + h) << 11) + s) * DKK + dk] = val;
                } else {
                    *(float2*)&out[(size_t)m * DD + e] = val;
                }
            }
        }
    }
}

// ---------------------------------------------------------------------------
// TF32 causal flash attention. Grid: (S/64, B*H). Block: 128 threads (4 warps).
// Q,K,V in [B,H,S,DK] fp32. Writes ctx in [B,S,D] (head concat).
// Warp w owns query rows [16w, 16w+16); full 64-key tiles.
// SA: Q staging -> K tile -> P tile (aliased). SV: V tile [key][dk].
// ---------------------------------------------------------------------------
#define AP 68   // smem row pad (floats)
__global__ __launch_bounds__(128) void attn_tc(const float* __restrict__ Q,
                                               const float* __restrict__ K,
                                               const float* __restrict__ V,
                                               float* __restrict__ ctx)
{
    __shared__ __align__(16) float SA[64][AP];
    __shared__ __align__(16) float SV[64][AP];

    const int tid  = threadIdx.x;
    const int lane = tid & 31;
    const int w    = tid >> 5;
    const int g    = lane >> 2;
    const int tig  = lane & 3;
    const int qt   = blockIdx.x;
    const int bh   = blockIdx.y;
    const int wrow = w << 4;

    const size_t base = (size_t)bh * SS * DKK;
    const float* Qb = Q + base + (size_t)qt * 64 * DKK;

    // stage Q (pre-scaled by 1/sqrt(64), tf32-rounded)
#pragma unroll
    for (int u = 0; u < 8; u++) {
        int idx = u * 128 + tid;
        int r = idx >> 4, c4 = idx & 15;
        float4 t = *(const float4*)(Qb + r * DKK + c4 * 4);
        uint4 s;
        s.x = __float_as_uint(to_tf32(t.x * 0.125f));
        s.y = __float_as_uint(to_tf32(t.y * 0.125f));
        s.z = __float_as_uint(to_tf32(t.z * 0.125f));
        s.w = __float_as_uint(to_tf32(t.w * 0.125f));
        *(uint4*)&SA[r][c4 * 4] = s;
    }
    __syncthreads();

    // Q a-fragments for all 8 k-steps (held in registers for whole block)
    float aQ[8][4];
#pragma unroll
    for (int ks = 0; ks < 8; ks++) {
        aQ[ks][0] = SA[wrow + g    ][ks * 8 + tig];
        aQ[ks][1] = SA[wrow + g + 8][ks * 8 + tig];
        aQ[ks][2] = SA[wrow + g    ][ks * 8 + tig + 4];
        aQ[ks][3] = SA[wrow + g + 8][ks * 8 + tig + 4];
    }

    float accO[8][4];
#pragma unroll
    for (int nf = 0; nf < 8; nf++)
#pragma unroll
        for (int r = 0; r < 4; r++) accO[nf][r] = 0.0f;
    float m0_ = -1e30f, m1_ = -1e30f, l0 = 0.0f, l1 = 0.0f;

    for (int kt = 0; kt <= qt; kt++) {
        __syncthreads();   // prior iter P reads / Q frag build complete
        const float* Kt = K + base + (size_t)kt * 64 * DKK;
        const float* Vt = V + base + (size_t)kt * 64 * DKK;
#pragma unroll
        for (int u = 0; u < 8; u++) {
            int idx = u * 128 + tid;
            int r = idx >> 4, c4 = idx & 15;
            float4 kv = *(const float4*)(Kt + r * DKK + c4 * 4);
            float4 vv = *(const float4*)(Vt + r * DKK + c4 * 4);
            uint4 s;
            s.x = __float_as_uint(to_tf32(kv.x)); s.y = __float_as_uint(to_tf32(kv.y));
            s.z = __float_as_uint(to_tf32(kv.z)); s.w = __float_as_uint(to_tf32(kv.w));
            *(uint4*)&SA[r][c4 * 4] = s;
            s.x = __float_as_uint(to_tf32(vv.x)); s.y = __float_as_uint(to_tf32(vv.y));
            s.z = __float_as_uint(to_tf32(vv.z)); s.w = __float_as_uint(to_tf32(vv.w));
            *(uint4*)&SV[r][c4 * 4] = s;
        }
        __syncthreads();

        // GEMM1: S(16x64) = Q(16x64) @ K^T   (B element (k=dk,n=key) = SA[key][dk])
        float sacc[8][4];
#pragma unroll
        for (int nf = 0; nf < 8; nf++)
#pragma unroll
            for (int r = 0; r < 4; r++) sacc[nf][r] = 0.0f;
#pragma unroll
        for (int ks = 0; ks < 8; ks++) {
#pragma unroll
            for (int nf = 0; nf < 8; nf++) {
                float b0 = SA[nf * 8 + g][ks * 8 + tig];
                float b1 = SA[nf * 8 + g][ks * 8 + tig + 4];
                mma8(sacc[nf], aQ[ks][0], aQ[ks][1], aQ[ks][2], aQ[ks][3], b0, b1);
            }
        }

        // causal mask on diagonal tile (relative row/col comparison valid: kt==qt)
        if (kt == qt) {
            int rg0 = wrow + g, rg1 = wrow + g + 8;
#pragma unroll
            for (int nf = 0; nf < 8; nf++) {
                int c0 = nf * 8 + tig * 2, c1 = c0 + 1;
                if (c0 > rg0) sacc[nf][0] = -1e30f;
                if (c1 > rg0) sacc[nf][1] = -1e30f;
                if (c0 > rg1) sacc[nf][2] = -1e30f;
                if (c1 > rg1) sacc[nf][3] = -1e30f;
            }
        }

        // online softmax (rows live in quads: reduce over lane^1, lane^2)
        float rm0 = -1e30f, rm1 = -1e30f;
#pragma unroll
        for (int nf = 0; nf < 8; nf++) {
            rm0 = fmaxf(rm0, fmaxf(sacc[nf][0], sacc[nf][1]));
            rm1 = fmaxf(rm1, fmaxf(sacc[nf][2], sacc[nf][3]));
        }
        rm0 = fmaxf(rm0, __shfl_xor_sync(0xFFFFFFFFu, rm0, 1));
        rm0 = fmaxf(rm0, __shfl_xor_sync(0xFFFFFFFFu, rm0, 2));
        rm1 = fmaxf(rm1, __shfl_xor_sync(0xFFFFFFFFu, rm1, 1));
        rm1 = fmaxf(rm1, __shfl_xor_sync(0xFFFFFFFFu, rm1, 2));
        float mn0 = fmaxf(m0_, rm0), mn1 = fmaxf(m1_, rm1);
        float al0 = __expf(m0_ - mn0), al1 = __expf(m1_ - mn1);
        float rs0 = 0.0f, rs1 = 0.0f;
#pragma unroll
        for (int nf = 0; nf < 8; nf++) {
            sacc[nf][0] = __expf(sacc[nf][0] - mn0);
            sacc[nf][1] = __expf(sacc[nf][1] - mn0);
            sacc[nf][2] = __expf(sacc[nf][2] - mn1);
            sacc[nf][3] = __expf(sacc[nf][3] - mn1);
            rs0 += sacc[nf][0] + sacc[nf][1];
            rs1 += sacc[nf][2] + sacc[nf][3];
        }
        rs0 += __shfl_xor_sync(0xFFFFFFFFu, rs0, 1);
        rs0 += __shfl_xor_sync(0xFFFFFFFFu, rs0, 2);
        rs1 += __shfl_xor_sync(0xFFFFFFFFu, rs1, 1);
        rs1 += __shfl_xor_sync(0xFFFFFFFFu, rs1, 2);
        l0 = l0 * al0 + rs0;
        l1 = l1 * al1 + rs1;
        m0_ = mn0; m1_ = mn1;
#pragma unroll
        for (int nf = 0; nf < 8; nf++) {
            accO[nf][0] *= al0; accO[nf][1] *= al0;
            accO[nf][2] *= al1; accO[nf][3] *= al1;
        }

        __syncthreads();   // all warps done reading SA as K
        // write P into SA [row][key] (warp-private rows)
#pragma unroll
        for (int nf = 0; nf < 8; nf++) {
            int c = nf * 8 + tig * 2;
            SA[wrow + g    ][c    ] = to_tf32(sacc[nf][0]);
            SA[wrow + g    ][c + 1] = to_tf32(sacc[nf][1]);
            SA[wrow + g + 8][c    ] = to_tf32(sacc[nf][2]);
            SA[wrow + g + 8][c + 1] = to_tf32(sacc[nf][3]);
        }
        __syncwarp();

        // GEMM2: O(16x64) += P(16x64) @ V(64x64)
        // A = P from SA (own rows); B element (k=key,n=dk) = SV[key][dk]
#pragma unroll
        for (int ks = 0; ks < 8; ks++) {
            float a0 = SA[wrow + g    ][ks * 8 + tig];
            float a1 = SA[wrow + g + 8][ks * 8 + tig];
            float a2 = SA[wrow + g    ][ks * 8 + tig + 4];
            float a3 = SA[wrow + g + 8][ks * 8 + tig + 4];
#pragma unroll
            for (int nf = 0; nf < 8; nf++) {
                float b0 = SV[ks * 8 + tig    ][nf * 8 + g];
                float b1 = SV[ks * 8 + tig + 4][nf * 8 + g];
                mma8(accO[nf], a0, a1, a2, a3, b0, b1);
            }
        }
    }

    // epilogue: normalize, write ctx [B,S,D] with head concat
    const int b = bh >> 4;
    const int h = bh & 15;
    float inv0 = 1.0f / l0, inv1 = 1.0f / l1;
    int s0 = (qt << 6) + wrow + g;
    int s1 = s0 + 8;
#pragma unroll
    for (int nf = 0; nf < 8; nf++) {
        int e = (h << 6) + (nf << 3) + (tig << 1);
        float2 v0, v1;
        v0.x = accO[nf][0] * inv0; v0.y = accO[nf][1] * inv0;
        v1.x = accO[nf][2] * inv1; v1.y = accO[nf][3] * inv1;
        *(float2*)&ctx[((size_t)b * SS + s0) * DD + e] = v0;
        *(float2*)&ctx[((size_t)b * SS + s1) * DD + e] = v1;
    }
}

// ---------------------------------------------------------------------------
extern "C" void kernel_launch(void* const* d_in, const int* in_sizes, int n_in,
                              void* d_out, int out_size)
{
    const float* q   = (const float*)d_in[0];
    const float* k   = (const float*)d_in[1];
    const float* v   = (const float*)d_in[2];
    // d_in[3] = mask (causal tril) — computed analytically in-kernel
    const float* w_q = (const float*)d_in[4];
    const float* w_k = (const float*)d_in[5];
    const float* w_v = (const float*)d_in[6];
    const float* w_o = (const float*)d_in[7];

    float* out  = (float*)d_out;
    float* keyh = out + OUT_PLANE;
    float* valh = out + 2 * (size_t)OUT_PLANE;

    float* qh = nullptr;
    float* ctx = nullptr;
    cudaGetSymbolAddress((void**)&qh, g_Qh);
    cudaGetSymbolAddress((void**)&ctx, g_ctx);

    dim3 ggrid(DD / 128, MM / 128);   // (8, 64)
    gemm_tc<<<ggrid, 256>>>(q, w_q, qh, 1);
    gemm_tc<<<ggrid, 256>>>(k, w_k, keyh, 1);
    gemm_tc<<<ggrid, 256>>>(v, w_v, valh, 1);

    dim3 agrid(SS / 64, BB * HH);     // (32, 64)
    attn_tc<<<agrid, 128>>>(qh, keyh, valh, ctx);

    gemm_tc<<<ggrid, 256>>>(ctx, w_o, out, 0);
}